// round 13
// baseline (speedup 1.0000x reference)
#include <cuda_runtime.h>
#include <cuda_bf16.h>
#include <cuda_fp16.h>
#include <cstdint>

// Problem constants
constexpr int B_  = 32;
constexpr int H_  = 12;
constexpr int W_  = 256;
constexpr int C_  = 256;
constexpr int HS_ = 4;            // H / SPLIT
constexpr int N_  = HS_ * W_;     // 1024 flattened spatial
constexpr int FC_ = 96;           // SPLIT * Cf
constexpr int HC_ = 768;          // SPLIT * C
constexpr int P_  = B_ * H_ * W_; // 98304 pixels

// Scratch (device globals) — all fp16
__device__ __half g_x16[(size_t)P_ * C_];          // 50 MB
__device__ __half g_Wt16[320 * 256];               // transposed concat [j][k]
__device__ __half g_f16[(size_t)B_ * N_ * FC_];    // 6.3 MB
__device__ __half g_g16[(size_t)B_ * N_ * FC_];    // 6.3 MB
__device__ __half g_s[(size_t)B_ * N_ * N_];       // 67 MB fp16 logits
__device__ __half g_beta[(size_t)B_ * N_ * N_];    // 64 MB  [b][n][m]
__device__ __half g_hT[(size_t)B_ * HC_ * N_];     // 48 MB  [b][c][n]

// ============================ PTX helpers ==================================
__device__ __forceinline__ uint32_t smem_u32(const void* p) {
    uint32_t a;
    asm("{ .reg .u64 t; cvta.to.shared.u64 t, %1; cvt.u32.u64 %0, t; }"
        : "=r"(a) : "l"(p));
    return a;
}
#define CP16(s, g) \
    asm volatile("cp.async.cg.shared.global [%0], [%1], 16;" \
        :: "r"(s), "l"(g) : "memory")
#define CPCOMMIT() asm volatile("cp.async.commit_group;" ::: "memory")
#define CPWAIT(n)  asm volatile("cp.async.wait_group %0;" :: "n"(n) : "memory")

__device__ __forceinline__ void ldsm_x4(uint32_t& r0, uint32_t& r1,
                                        uint32_t& r2, uint32_t& r3, uint32_t addr) {
    asm volatile("ldmatrix.sync.aligned.m8n8.x4.shared.b16 {%0,%1,%2,%3}, [%4];"
        : "=r"(r0), "=r"(r1), "=r"(r2), "=r"(r3) : "r"(addr));
}
__device__ __forceinline__ void mma_fp16(float* c, const uint32_t* a, const uint32_t* b) {
    asm volatile("mma.sync.aligned.m16n8k16.row.col.f32.f16.f16.f32 "
        "{%0,%1,%2,%3}, {%4,%5,%6,%7}, {%8,%9}, {%0,%1,%2,%3};"
        : "+f"(c[0]), "+f"(c[1]), "+f"(c[2]), "+f"(c[3])
        : "r"(a[0]), "r"(a[1]), "r"(a[2]), "r"(a[3]), "r"(b[0]), "r"(b[1]));
}
// smem tile: 64B rows (32 x b16), 4x16B chunks/row, XOR swizzle for ldmatrix
__device__ __forceinline__ uint32_t swz(int r, int c) {
    return (uint32_t)(r * 64 + ((c ^ ((r >> 1) & 3)) << 4));
}

// ---------------------------------------------------------------------------
// Kernel 0a: convert x -> fp16
// ---------------------------------------------------------------------------
__global__ __launch_bounds__(256) void k_cvt_x(const float* __restrict__ x)
{
    size_t gid = (size_t)blockIdx.x * 256 + threadIdx.x;   // float4 index
    float4 v = reinterpret_cast<const float4*>(x)[gid];
    uint2 pk;
    reinterpret_cast<__half2*>(&pk)[0] = __float22half2_rn(make_float2(v.x, v.y));
    reinterpret_cast<__half2*>(&pk)[1] = __float22half2_rn(make_float2(v.z, v.w));
    reinterpret_cast<uint2*>(g_x16)[gid] = pk;
}

// ---------------------------------------------------------------------------
// Kernel 0b: build transposed fp16 concat weight Wt[j][k], j in [0,320)
// ---------------------------------------------------------------------------
__global__ __launch_bounds__(256) void k_cvt_w(
    const float* __restrict__ Wf, const float* __restrict__ Wg,
    const float* __restrict__ Wh)
{
    const int j = blockIdx.x;
    const int k = threadIdx.x;
    float v;
    if (j < 256)      v = Wh[k * 256 + j];
    else if (j < 288) v = Wf[k * 32 + (j - 256)];
    else              v = Wg[k * 32 + (j - 288)];
    g_Wt16[j * 256 + k] = __float2half(v);
}

// ---------------------------------------------------------------------------
// Kernel 1: merged projections via 1-pass fp16 HMMA.
// C[P,320] = X[P,256] @ Wt^T. Tile 128(p) x 64(c), K=256 in 8 chunks.
// 8 warps (4m x 2n). Epilogue: h-blocks -> smem transpose -> g_hT (fp16);
// f/g block -> fp16 scatter.
// ---------------------------------------------------------------------------
constexpr int PJ_STAGE = 12288;   // A fp16 8K + B fp16 4K
constexpr int PJ_STGS  = 3;
constexpr int TS_ = 136;          // transpose staging pitch (halves)

__global__ __launch_bounds__(256) void k_proj()
{
    extern __shared__ char smem[];
    const uint32_t sbase = smem_u32(smem);
    const int tid  = threadIdx.x;
    const int wid  = tid >> 5;
    const int lane = tid & 31;
    const int wm   = wid & 3;
    const int wn   = wid >> 2;
    const int cBase = blockIdx.x * 64;     // 0..4 (h: 0..3, f/g: 4)
    const int pBase = blockIdx.y * 128;

    const __half* gA = g_x16 + (size_t)pBase * 256;
    const __half* gB = g_Wt16 + (size_t)cBase * 256;

    const int arow = tid >> 2, ac = tid & 3;
    auto issue = [&](int slot, int kc) {
        const uint32_t st = sbase + slot * PJ_STAGE;
#pragma unroll
        for (int i = 0; i < 2; i++) {
            int idx = i * 256 + tid;
            int r = idx >> 2, c = idx & 3;
            CP16(st + swz(r, c), gA + (size_t)r * 256 + kc * 32 + c * 8);
        }
        CP16(st + 8192 + swz(arow, ac), gB + (size_t)arow * 256 + kc * 32 + ac * 8);
    };

    float acc[2][4][4];
#pragma unroll
    for (int mt = 0; mt < 2; mt++)
#pragma unroll
        for (int nt = 0; nt < 4; nt++)
#pragma unroll
            for (int j = 0; j < 4; j++) acc[mt][nt][j] = 0.f;

    issue(0, 0); CPCOMMIT();
    issue(1, 1); CPCOMMIT();

    for (int kc = 0; kc < 8; kc++) {
        if (kc + 2 < 8) {
            issue((kc + 2) % PJ_STGS, kc + 2); CPCOMMIT();
            CPWAIT(2);
        } else {
            CPWAIT(0);
        }
        __syncthreads();
        const uint32_t st = sbase + (kc % PJ_STGS) * PJ_STAGE;
#pragma unroll
        for (int ks = 0; ks < 2; ks++) {
            uint32_t af[2][4];
#pragma unroll
            for (int mt = 0; mt < 2; mt++) {
                int row = wm * 32 + mt * 16 + ((lane >> 3) & 1) * 8 + (lane & 7);
                int ch  = ks * 2 + (lane >> 4);
                ldsm_x4(af[mt][0], af[mt][1], af[mt][2], af[mt][3], st + swz(row, ch));
            }
            uint32_t bf[4][2];
#pragma unroll
            for (int p = 0; p < 2; p++) {
                int row = wn * 32 + p * 16 + (lane >> 4) * 8 + (lane & 7);
                int ch  = ks * 2 + ((lane >> 3) & 1);
                uint32_t r0, r1, r2, r3;
                ldsm_x4(r0, r1, r2, r3, st + 8192 + swz(row, ch));
                bf[2 * p][0] = r0; bf[2 * p][1] = r1;
                bf[2 * p + 1][0] = r2; bf[2 * p + 1][1] = r3;
            }
#pragma unroll
            for (int mt = 0; mt < 2; mt++)
#pragma unroll
                for (int nt = 0; nt < 4; nt++)
                    mma_fp16(acc[mt][nt], af[mt], bf[nt]);
        }
        __syncthreads();
    }

    // Geometry: 128 consecutive pixels = fixed (b, h), 128 consecutive w.
    const int gr = lane >> 2;
    const int qc = (lane & 3) * 2;
    const int bb  = pBase / (H_ * W_);
    const int rem = pBase - bb * (H_ * W_);
    const int hpx = rem >> 8;
    const int w0  = rem & 255;
    const int sg  = hpx >> 2;
    const int hr  = hpx & 3;
    const int n0  = hr * W_ + w0;

    if (cBase < 256) {
        // h path: stage transposed [c=64][n=128] in smem, write g_hT coalesced
        __half* ts = reinterpret_cast<__half*>(smem);
#pragma unroll
        for (int mt = 0; mt < 2; mt++)
#pragma unroll
            for (int rr = 0; rr < 2; rr++) {
                int nl = wm * 32 + mt * 16 + rr * 8 + gr;
#pragma unroll
                for (int nt = 0; nt < 4; nt++) {
                    int cl = wn * 32 + nt * 8 + qc;
                    ts[cl * TS_ + nl]       = __float2half(acc[mt][nt][rr * 2 + 0]);
                    ts[(cl + 1) * TS_ + nl] = __float2half(acc[mt][nt][rr * 2 + 1]);
                }
            }
        __syncthreads();
        const size_t hTrow0 = ((size_t)bb * HC_ + sg * 256 + cBase) * N_ + n0;
#pragma unroll
        for (int i = 0; i < 4; i++) {
            int idx = i * 256 + tid;
            int r = idx >> 4, u = idx & 15;
            uint4 v = *reinterpret_cast<const uint4*>(&ts[r * TS_ + u * 8]);
            *reinterpret_cast<uint4*>(&g_hT[hTrow0 + (size_t)r * N_ + u * 8]) = v;
        }
    } else {
        // f/g path: fp16 scatter
#pragma unroll
        for (int mt = 0; mt < 2; mt++)
#pragma unroll
            for (int rr = 0; rr < 2; rr++) {
                int nl = wm * 32 + mt * 16 + rr * 8 + gr;
                int n  = n0 + nl;
                size_t base = ((size_t)bb * N_ + n) * FC_ + sg * 32;
#pragma unroll
                for (int nt = 0; nt < 4; nt++) {
                    int j = cBase + wn * 32 + nt * 8 + qc;   // 256..319
                    __half2 hv = __float22half2_rn(
                        make_float2(acc[mt][nt][rr * 2 + 0], acc[mt][nt][rr * 2 + 1]));
                    if (j < 288)
                        *reinterpret_cast<__half2*>(&g_f16[base + (j - 256)]) = hv;
                    else
                        *reinterpret_cast<__half2*>(&g_g16[base + (j - 288)]) = hv;
                }
            }
    }
}

// ---------------------------------------------------------------------------
// Kernel 2: s[b] = g_fl[b] @ f_fl[b]^T, streaming fp16 HMMA.
// CTA = 128 g-rows x FULL 1024 f-cols. A resident (24 KB), B double-buffered
// (2 x 24 KB), prefetch overlaps compute. Per-chunk fp16 s epilogue.
// Grid: (N/128, B) = 256 CTAs, 2 CTAs/SM.
// ---------------------------------------------------------------------------
constexpr int SC_BUF = 24576;   // 3 subtiles x 8KB

__global__ __launch_bounds__(256) void k_score_mma()
{
    extern __shared__ char smem[];
    const uint32_t sbase = smem_u32(smem);
    const int tid  = threadIdx.x;
    const int wid  = tid >> 5;
    const int lane = tid & 31;
    const int wm   = wid & 3;
    const int wn   = wid >> 2;
    const int b     = blockIdx.y;
    const int nBase = blockIdx.x * 128;   // rows of s (g index)

    const __half* srcA = g_g16 + ((size_t)b * N_ + nBase) * FC_;
    const __half* srcB = g_f16 + (size_t)b * N_ * FC_;

    const uint32_t AS = sbase;
    const uint32_t BS0 = sbase + SC_BUF;

    auto issueA = [&]() {
#pragma unroll
        for (int t = 0; t < 3; t++)
#pragma unroll
            for (int i = 0; i < 2; i++) {
                int idx = i * 256 + tid;
                int r = idx >> 2, c = idx & 3;
                CP16(AS + t * 8192 + swz(r, c), srcA + (size_t)r * FC_ + t * 32 + c * 8);
            }
    };
    auto issueB = [&](int buf, int mc) {
        const uint32_t bs = BS0 + buf * SC_BUF;
        const __half* src = srcB + (size_t)(mc * 128) * FC_;
#pragma unroll
        for (int t = 0; t < 3; t++)
#pragma unroll
            for (int i = 0; i < 2; i++) {
                int idx = i * 256 + tid;
                int r = idx >> 2, c = idx & 3;
                CP16(bs + t * 8192 + swz(r, c), src + (size_t)r * FC_ + t * 32 + c * 8);
            }
    };

    issueA(); issueB(0, 0); CPCOMMIT();   // group 0
    issueB(1, 1); CPCOMMIT();             // group 1

    __half* sp = g_s + (size_t)b * N_ * N_;
    const int gr = lane >> 2;
    const int qc = (lane & 3) * 2;

    for (int mc = 0; mc < 8; mc++) {
        if (mc < 7) { CPWAIT(1); } else { CPWAIT(0); }
        __syncthreads();

        const uint32_t BS = BS0 + (mc & 1) * SC_BUF;
        float acc[2][8][4];
#pragma unroll
        for (int mt = 0; mt < 2; mt++)
#pragma unroll
            for (int nt = 0; nt < 8; nt++)
#pragma unroll
                for (int j = 0; j < 4; j++) acc[mt][nt][j] = 0.f;

#pragma unroll
        for (int t = 0; t < 3; t++) {
#pragma unroll
            for (int ks = 0; ks < 2; ks++) {
                uint32_t af[2][4];
#pragma unroll
                for (int mt = 0; mt < 2; mt++) {
                    int row = wm * 32 + mt * 16 + ((lane >> 3) & 1) * 8 + (lane & 7);
                    int ch  = ks * 2 + (lane >> 4);
                    ldsm_x4(af[mt][0], af[mt][1], af[mt][2], af[mt][3],
                            AS + t * 8192 + swz(row, ch));
                }
                uint32_t bf[8][2];
#pragma unroll
                for (int p = 0; p < 4; p++) {
                    int row = wn * 64 + p * 16 + (lane >> 4) * 8 + (lane & 7);
                    int ch  = ks * 2 + ((lane >> 3) & 1);
                    uint32_t r0, r1, r2, r3;
                    ldsm_x4(r0, r1, r2, r3, BS + t * 8192 + swz(row, ch));
                    bf[2 * p][0] = r0; bf[2 * p][1] = r1;
                    bf[2 * p + 1][0] = r2; bf[2 * p + 1][1] = r3;
                }
#pragma unroll
                for (int mt = 0; mt < 2; mt++)
#pragma unroll
                    for (int nt = 0; nt < 8; nt++)
                        mma_fp16(acc[mt][nt], af[mt], bf[nt]);
            }
        }

        // Per-chunk epilogue: fp16 s tile [128 rows x 128 cols at mc*128]
#pragma unroll
        for (int mt = 0; mt < 2; mt++)
#pragma unroll
            for (int rr = 0; rr < 2; rr++) {
                int n = nBase + wm * 32 + mt * 16 + rr * 8 + gr;
#pragma unroll
                for (int nt = 0; nt < 8; nt++) {
                    int m = mc * 128 + wn * 64 + nt * 8 + qc;
                    __half2 v = __float22half2_rn(
                        make_float2(acc[mt][nt][rr * 2], acc[mt][nt][rr * 2 + 1]));
                    *reinterpret_cast<__half2*>(&sp[(size_t)n * N_ + m]) = v;
                }
            }
        __syncthreads();   // all warps done reading BS before reissue

        if (mc + 2 < 8) { issueB(mc & 1, mc + 2); CPCOMMIT(); }
    }
}

// ---------------------------------------------------------------------------
// Kernel 3: warp-per-row softmax over fp16 logits; writes fp16 beta.
// Each lane: 4 x uint4 = 32 halves. No smem, no block syncs.
// ---------------------------------------------------------------------------
__global__ __launch_bounds__(256) void k_softmax()
{
    const int wid  = threadIdx.x >> 5;
    const int lane = threadIdx.x & 31;
    const size_t row = (size_t)blockIdx.x * 8 + wid;
    const uint4* sp = reinterpret_cast<const uint4*>(g_s + row * N_);

    uint4 raw[4];
#pragma unroll
    for (int i = 0; i < 4; i++) raw[i] = sp[lane + 32 * i];

    float v[32];
#pragma unroll
    for (int i = 0; i < 4; i++) {
        const __half2* h2 = reinterpret_cast<const __half2*>(&raw[i]);
#pragma unroll
        for (int j = 0; j < 4; j++) {
            float2 f = __half22float2(h2[j]);
            v[i * 8 + j * 2]     = f.x;
            v[i * 8 + j * 2 + 1] = f.y;
        }
    }

    float m = -1e30f;
#pragma unroll
    for (int i = 0; i < 32; i++) m = fmaxf(m, v[i]);
#pragma unroll
    for (int o = 16; o > 0; o >>= 1)
        m = fmaxf(m, __shfl_xor_sync(0xFFFFFFFF, m, o));

    float sum = 0.f;
#pragma unroll
    for (int i = 0; i < 32; i++) { v[i] = __expf(v[i] - m); sum += v[i]; }
#pragma unroll
    for (int o = 16; o > 0; o >>= 1)
        sum += __shfl_xor_sync(0xFFFFFFFF, sum, o);
    const float inv = 1.0f / sum;

    uint4* bp = reinterpret_cast<uint4*>(g_beta + row * N_);
#pragma unroll
    for (int i = 0; i < 4; i++) {
        uint4 pk;
        __half2* h2 = reinterpret_cast<__half2*>(&pk);
#pragma unroll
        for (int j = 0; j < 4; j++)
            h2[j] = __float22half2_rn(make_float2(v[i * 8 + j * 2] * inv,
                                                  v[i * 8 + j * 2 + 1] * inv));
        bp[lane + 32 * i] = pk;
    }
}

// ---------------------------------------------------------------------------
// Kernel 4: fp16 HMMA GEMM  o[b] = beta[b] @ h_fl[b]  (M=1024, N=768, K=1024)
// CTA tile 128x128x32, 8 warps. 4-stage cp.async pipeline.
// Epilogue fuses hw_recover + gamma*o + x.
// ---------------------------------------------------------------------------
constexpr int BK_    = 32;
constexpr int NK_    = N_ / BK_;   // 32 k-chunks
constexpr int STAGE_ = 16384;      // 8KB A + 8KB B per stage
constexpr int STGS_  = 4;

__global__ __launch_bounds__(256) void k_o_mma(
    const float* __restrict__ x, const float* __restrict__ gammaP,
    float* __restrict__ out)
{
    extern __shared__ char smem[];
    const uint32_t sbase = smem_u32(smem);

    const int tid  = threadIdx.x;
    const int wid  = tid >> 5;
    const int lane = tid & 31;
    const int wm   = wid & 3;
    const int wn   = wid >> 2;
    const int b     = blockIdx.z;
    const int mBase = blockIdx.y * 128;
    const int cBase = blockIdx.x * 128;

    const __half* gA = g_beta + ((size_t)b * N_ + mBase) * N_;
    const __half* gB = g_hT  + ((size_t)b * HC_ + cBase) * N_;

    const int lr = tid >> 2;
    const int lc = tid & 3;

    auto issue = [&](int slot, int kc) {
        const uint32_t aS = sbase + slot * STAGE_;
        const uint32_t bS = aS + 8192;
        const int kOff = kc * BK_ + lc * 8;
#pragma unroll
        for (int i = 0; i < 2; i++) {
            int r = lr + i * 64;
            CP16(aS + swz(r, lc), gA + (size_t)r * N_ + kOff);
        }
#pragma unroll
        for (int i = 0; i < 2; i++) {
            int r = lr + i * 64;
            CP16(bS + swz(r, lc), gB + (size_t)r * N_ + kOff);
        }
    };

    float acc[2][8][4];
#pragma unroll
    for (int mt = 0; mt < 2; mt++)
#pragma unroll
        for (int nt = 0; nt < 8; nt++)
#pragma unroll
            for (int j = 0; j < 4; j++) acc[mt][nt][j] = 0.f;

    issue(0, 0); CPCOMMIT();
    issue(1, 1); CPCOMMIT();
    issue(2, 2); CPCOMMIT();

    for (int kc = 0; kc < NK_; kc++) {
        if (kc + 3 < NK_) {
            issue((kc + 3) % STGS_, kc + 3); CPCOMMIT();
            CPWAIT(3);
        } else {
            CPWAIT(0);
        }
        __syncthreads();

        const uint32_t aS = sbase + (kc % STGS_) * STAGE_;
        const uint32_t bS = aS + 8192;
#pragma unroll
        for (int ks = 0; ks < 2; ks++) {
            uint32_t afr[2][4];
#pragma unroll
            for (int mt = 0; mt < 2; mt++) {
                int row = wm * 32 + mt * 16 + ((lane >> 3) & 1) * 8 + (lane & 7);
                int ch  = ks * 2 + (lane >> 4);
                ldsm_x4(afr[mt][0], afr[mt][1], afr[mt][2], afr[mt][3],
                        aS + swz(row, ch));
            }
            uint32_t bfr[8][2];
#pragma unroll
            for (int p = 0; p < 4; p++) {
                int row = wn * 64 + p * 16 + (lane >> 4) * 8 + (lane & 7);
                int ch  = ks * 2 + ((lane >> 3) & 1);
                uint32_t r0, r1, r2, r3;
                ldsm_x4(r0, r1, r2, r3, bS + swz(row, ch));
                bfr[2 * p][0] = r0; bfr[2 * p][1] = r1;
                bfr[2 * p + 1][0] = r2; bfr[2 * p + 1][1] = r3;
            }
#pragma unroll
            for (int mt = 0; mt < 2; mt++)
#pragma unroll
                for (int nt = 0; nt < 8; nt++)
                    mma_fp16(acc[mt][nt], afr[mt], bfr[nt]);
        }
        __syncthreads();
    }

    const float gamma = __ldg(gammaP);
    const int gr = lane >> 2;
    const int qc = (lane & 3) * 2;
#pragma unroll
    for (int mt = 0; mt < 2; mt++) {
#pragma unroll
        for (int rr = 0; rr < 2; rr++) {
            int m    = mBase + wm * 32 + mt * 16 + rr * 8 + gr;
            int hr   = m >> 8;
            int wpix = m & 255;
#pragma unroll
            for (int nt = 0; nt < 8; nt++) {
                int cg = cBase + wn * 64 + nt * 8 + qc;
                int sg = cg >> 8;
                int ch = cg & 255;
                int hh = sg * HS_ + hr;
                size_t idx = (((size_t)b * H_ + hh) * W_ + wpix) * C_ + ch;
                float2 xv = *reinterpret_cast<const float2*>(x + idx);
                float2 o;
                o.x = fmaf(gamma, acc[mt][nt][rr * 2 + 0], xv.x);
                o.y = fmaf(gamma, acc[mt][nt][rr * 2 + 1], xv.y);
                *reinterpret_cast<float2*>(out + idx) = o;
            }
        }
    }
}

// ---------------------------------------------------------------------------
extern "C" void kernel_launch(void* const* d_in, const int* in_sizes, int n_in,
                              void* d_out, int out_size)
{
    const float* x     = (const float*)d_in[0];
    const float* Wf    = (const float*)d_in[1];
    const float* Wg    = (const float*)d_in[2];
    const float* Wh    = (const float*)d_in[3];
    const float* gamma = (const float*)d_in[4];
    float* out = (float*)d_out;

    static bool attrSet = false;
    if (!attrSet) {
        cudaFuncSetAttribute(k_proj, cudaFuncAttributeMaxDynamicSharedMemorySize,
                             PJ_STGS * PJ_STAGE);
        cudaFuncSetAttribute(k_score_mma, cudaFuncAttributeMaxDynamicSharedMemorySize,
                             3 * SC_BUF);
        cudaFuncSetAttribute(k_o_mma, cudaFuncAttributeMaxDynamicSharedMemorySize,
                             STGS_ * STAGE_);
        attrSet = true;
    }

    k_cvt_x    <<<P_ * C_ / 4 / 256, 256>>>(x);
    k_cvt_w    <<<320, 256>>>(Wf, Wg, Wh);
    k_proj     <<<dim3(5, P_ / 128), 256, PJ_STGS * PJ_STAGE>>>();
    k_score_mma<<<dim3(N_ / 128, B_), 256, 3 * SC_BUF>>>();
    k_softmax  <<<B_ * N_ / 8, 256>>>();
    k_o_mma    <<<dim3(HC_ / 128, N_ / 128, B_), 256,
                  STGS_ * STAGE_>>>(x, gamma, out);
}

// round 14
// speedup vs baseline: 1.0043x; 1.0043x over previous
#include <cuda_runtime.h>
#include <cuda_bf16.h>
#include <cuda_fp16.h>
#include <cstdint>

// Problem constants
constexpr int B_  = 32;
constexpr int H_  = 12;
constexpr int W_  = 256;
constexpr int C_  = 256;
constexpr int HS_ = 4;            // H / SPLIT
constexpr int N_  = HS_ * W_;     // 1024 flattened spatial
constexpr int FC_ = 96;           // SPLIT * Cf
constexpr int HC_ = 768;          // SPLIT * C
constexpr int P_  = B_ * H_ * W_; // 98304 pixels

// Scratch (device globals) — all fp16
__device__ __half g_x16[(size_t)P_ * C_];          // 50 MB
__device__ __half g_Wt16[320 * 256];               // transposed concat [j][k]
__device__ __half g_f16[(size_t)B_ * N_ * FC_];    // 6.3 MB
__device__ __half g_g16[(size_t)B_ * N_ * FC_];    // 6.3 MB
__device__ __half g_s[(size_t)B_ * N_ * N_];       // 67 MB fp16 logits
__device__ __half g_beta[(size_t)B_ * N_ * N_];    // 64 MB  [b][n][m]
__device__ __half g_hT[(size_t)B_ * HC_ * N_];     // 48 MB  [b][c][n]

// ============================ PTX helpers ==================================
__device__ __forceinline__ uint32_t smem_u32(const void* p) {
    uint32_t a;
    asm("{ .reg .u64 t; cvta.to.shared.u64 t, %1; cvt.u32.u64 %0, t; }"
        : "=r"(a) : "l"(p));
    return a;
}
#define CP16(s, g) \
    asm volatile("cp.async.cg.shared.global [%0], [%1], 16;" \
        :: "r"(s), "l"(g) : "memory")
#define CPCOMMIT() asm volatile("cp.async.commit_group;" ::: "memory")
#define CPWAIT(n)  asm volatile("cp.async.wait_group %0;" :: "n"(n) : "memory")

__device__ __forceinline__ void ldsm_x4(uint32_t& r0, uint32_t& r1,
                                        uint32_t& r2, uint32_t& r3, uint32_t addr) {
    asm volatile("ldmatrix.sync.aligned.m8n8.x4.shared.b16 {%0,%1,%2,%3}, [%4];"
        : "=r"(r0), "=r"(r1), "=r"(r2), "=r"(r3) : "r"(addr));
}
__device__ __forceinline__ void mma_fp16(float* c, const uint32_t* a, const uint32_t* b) {
    asm volatile("mma.sync.aligned.m16n8k16.row.col.f32.f16.f16.f32 "
        "{%0,%1,%2,%3}, {%4,%5,%6,%7}, {%8,%9}, {%0,%1,%2,%3};"
        : "+f"(c[0]), "+f"(c[1]), "+f"(c[2]), "+f"(c[3])
        : "r"(a[0]), "r"(a[1]), "r"(a[2]), "r"(a[3]), "r"(b[0]), "r"(b[1]));
}
// smem tile: 64B rows (32 x b16), 4x16B chunks/row, XOR swizzle for ldmatrix
__device__ __forceinline__ uint32_t swz(int r, int c) {
    return (uint32_t)(r * 64 + ((c ^ ((r >> 1) & 3)) << 4));
}

// ---------------------------------------------------------------------------
// Kernel 0a: convert x -> fp16
// ---------------------------------------------------------------------------
__global__ __launch_bounds__(256) void k_cvt_x(const float* __restrict__ x)
{
    size_t gid = (size_t)blockIdx.x * 256 + threadIdx.x;   // float4 index
    float4 v = reinterpret_cast<const float4*>(x)[gid];
    uint2 pk;
    reinterpret_cast<__half2*>(&pk)[0] = __float22half2_rn(make_float2(v.x, v.y));
    reinterpret_cast<__half2*>(&pk)[1] = __float22half2_rn(make_float2(v.z, v.w));
    reinterpret_cast<uint2*>(g_x16)[gid] = pk;
}

// ---------------------------------------------------------------------------
// Kernel 0b: build transposed fp16 concat weight Wt[j][k], j in [0,320)
// ---------------------------------------------------------------------------
__global__ __launch_bounds__(256) void k_cvt_w(
    const float* __restrict__ Wf, const float* __restrict__ Wg,
    const float* __restrict__ Wh)
{
    const int j = blockIdx.x;
    const int k = threadIdx.x;
    float v;
    if (j < 256)      v = Wh[k * 256 + j];
    else if (j < 288) v = Wf[k * 32 + (j - 256)];
    else              v = Wg[k * 32 + (j - 288)];
    g_Wt16[j * 256 + k] = __float2half(v);
}

// ---------------------------------------------------------------------------
// Kernel 1: merged projections via 1-pass fp16 HMMA, BK=64.
// C[P,320] = X[P,256] @ Wt^T. Tile 128(p) x 64(c), K=256 in 4 chunks of 64.
// Stage = A 16KB (2 subtiles) + B 8KB (2 subtiles) = 24KB, 3 stages.
// Epilogue: h-blocks -> smem transpose -> g_hT (fp16); f/g -> fp16 scatter.
// ---------------------------------------------------------------------------
constexpr int PJ_STAGE = 24576;   // A 16K + B 8K
constexpr int PJ_STGS  = 3;
constexpr int TS_ = 136;          // transpose staging pitch (halves)

__global__ __launch_bounds__(256) void k_proj()
{
    extern __shared__ char smem[];
    const uint32_t sbase = smem_u32(smem);
    const int tid  = threadIdx.x;
    const int wid  = tid >> 5;
    const int lane = tid & 31;
    const int wm   = wid & 3;
    const int wn   = wid >> 2;
    const int cBase = blockIdx.x * 64;     // 0..4 (h: 0..3, f/g: 4)
    const int pBase = blockIdx.y * 128;

    const __half* gA = g_x16 + (size_t)pBase * 256;
    const __half* gB = g_Wt16 + (size_t)cBase * 256;

    const int arow = tid >> 2, ac = tid & 3;
    auto issue = [&](int slot, int kc) {
        const uint32_t st = sbase + slot * PJ_STAGE;
#pragma unroll
        for (int ksub = 0; ksub < 2; ksub++) {
            const int kOff = kc * 64 + ksub * 32;
#pragma unroll
            for (int i = 0; i < 2; i++) {
                int idx = i * 256 + tid;
                int r = idx >> 2, c = idx & 3;
                CP16(st + ksub * 8192 + swz(r, c),
                     gA + (size_t)r * 256 + kOff + c * 8);
            }
            CP16(st + 16384 + ksub * 4096 + swz(arow, ac),
                 gB + (size_t)arow * 256 + kOff + ac * 8);
        }
    };

    float acc[2][4][4];
#pragma unroll
    for (int mt = 0; mt < 2; mt++)
#pragma unroll
        for (int nt = 0; nt < 4; nt++)
#pragma unroll
            for (int j = 0; j < 4; j++) acc[mt][nt][j] = 0.f;

    issue(0, 0); CPCOMMIT();
    issue(1, 1); CPCOMMIT();

    for (int kc = 0; kc < 4; kc++) {
        if (kc + 2 < 4) {
            issue((kc + 2) % PJ_STGS, kc + 2); CPCOMMIT();
            CPWAIT(2);
        } else {
            CPWAIT(0);
        }
        __syncthreads();
        const uint32_t st = sbase + (kc % PJ_STGS) * PJ_STAGE;
#pragma unroll
        for (int ksub = 0; ksub < 2; ksub++) {
            const uint32_t aT = st + ksub * 8192;
            const uint32_t bT = st + 16384 + ksub * 4096;
#pragma unroll
            for (int ks = 0; ks < 2; ks++) {
                uint32_t af[2][4];
#pragma unroll
                for (int mt = 0; mt < 2; mt++) {
                    int row = wm * 32 + mt * 16 + ((lane >> 3) & 1) * 8 + (lane & 7);
                    int ch  = ks * 2 + (lane >> 4);
                    ldsm_x4(af[mt][0], af[mt][1], af[mt][2], af[mt][3],
                            aT + swz(row, ch));
                }
                uint32_t bf[4][2];
#pragma unroll
                for (int p = 0; p < 2; p++) {
                    int row = wn * 32 + p * 16 + (lane >> 4) * 8 + (lane & 7);
                    int ch  = ks * 2 + ((lane >> 3) & 1);
                    uint32_t r0, r1, r2, r3;
                    ldsm_x4(r0, r1, r2, r3, bT + swz(row, ch));
                    bf[2 * p][0] = r0; bf[2 * p][1] = r1;
                    bf[2 * p + 1][0] = r2; bf[2 * p + 1][1] = r3;
                }
#pragma unroll
                for (int mt = 0; mt < 2; mt++)
#pragma unroll
                    for (int nt = 0; nt < 4; nt++)
                        mma_fp16(acc[mt][nt], af[mt], bf[nt]);
            }
        }
        __syncthreads();
    }

    // Geometry: 128 consecutive pixels = fixed (b, h), 128 consecutive w.
    const int gr = lane >> 2;
    const int qc = (lane & 3) * 2;
    const int bb  = pBase / (H_ * W_);
    const int rem = pBase - bb * (H_ * W_);
    const int hpx = rem >> 8;
    const int w0  = rem & 255;
    const int sg  = hpx >> 2;
    const int hr  = hpx & 3;
    const int n0  = hr * W_ + w0;

    if (cBase < 256) {
        // h path: stage transposed [c=64][n=128] in smem, write g_hT coalesced
        __half* ts = reinterpret_cast<__half*>(smem);
#pragma unroll
        for (int mt = 0; mt < 2; mt++)
#pragma unroll
            for (int rr = 0; rr < 2; rr++) {
                int nl = wm * 32 + mt * 16 + rr * 8 + gr;
#pragma unroll
                for (int nt = 0; nt < 4; nt++) {
                    int cl = wn * 32 + nt * 8 + qc;
                    ts[cl * TS_ + nl]       = __float2half(acc[mt][nt][rr * 2 + 0]);
                    ts[(cl + 1) * TS_ + nl] = __float2half(acc[mt][nt][rr * 2 + 1]);
                }
            }
        __syncthreads();
        const size_t hTrow0 = ((size_t)bb * HC_ + sg * 256 + cBase) * N_ + n0;
#pragma unroll
        for (int i = 0; i < 4; i++) {
            int idx = i * 256 + tid;
            int r = idx >> 4, u = idx & 15;
            uint4 v = *reinterpret_cast<const uint4*>(&ts[r * TS_ + u * 8]);
            *reinterpret_cast<uint4*>(&g_hT[hTrow0 + (size_t)r * N_ + u * 8]) = v;
        }
    } else {
        // f/g path: fp16 scatter
#pragma unroll
        for (int mt = 0; mt < 2; mt++)
#pragma unroll
            for (int rr = 0; rr < 2; rr++) {
                int nl = wm * 32 + mt * 16 + rr * 8 + gr;
                int n  = n0 + nl;
                size_t base = ((size_t)bb * N_ + n) * FC_ + sg * 32;
#pragma unroll
                for (int nt = 0; nt < 4; nt++) {
                    int j = cBase + wn * 32 + nt * 8 + qc;   // 256..319
                    __half2 hv = __float22half2_rn(
                        make_float2(acc[mt][nt][rr * 2 + 0], acc[mt][nt][rr * 2 + 1]));
                    if (j < 288)
                        *reinterpret_cast<__half2*>(&g_f16[base + (j - 256)]) = hv;
                    else
                        *reinterpret_cast<__half2*>(&g_g16[base + (j - 288)]) = hv;
                }
            }
    }
}

// ---------------------------------------------------------------------------
// Kernel 2: s[b] = g_fl[b] @ f_fl[b]^T, streaming fp16 HMMA.
// CTA = 128 g-rows x FULL 1024 f-cols. A resident (24 KB), B double-buffered
// (2 x 24 KB), prefetch overlaps compute. Per-chunk fp16 s epilogue.
// ---------------------------------------------------------------------------
constexpr int SC_BUF = 24576;   // 3 subtiles x 8KB

__global__ __launch_bounds__(256) void k_score_mma()
{
    extern __shared__ char smem[];
    const uint32_t sbase = smem_u32(smem);
    const int tid  = threadIdx.x;
    const int wid  = tid >> 5;
    const int lane = tid & 31;
    const int wm   = wid & 3;
    const int wn   = wid >> 2;
    const int b     = blockIdx.y;
    const int nBase = blockIdx.x * 128;   // rows of s (g index)

    const __half* srcA = g_g16 + ((size_t)b * N_ + nBase) * FC_;
    const __half* srcB = g_f16 + (size_t)b * N_ * FC_;

    const uint32_t AS = sbase;
    const uint32_t BS0 = sbase + SC_BUF;

    auto issueA = [&]() {
#pragma unroll
        for (int t = 0; t < 3; t++)
#pragma unroll
            for (int i = 0; i < 2; i++) {
                int idx = i * 256 + tid;
                int r = idx >> 2, c = idx & 3;
                CP16(AS + t * 8192 + swz(r, c), srcA + (size_t)r * FC_ + t * 32 + c * 8);
            }
    };
    auto issueB = [&](int buf, int mc) {
        const uint32_t bs = BS0 + buf * SC_BUF;
        const __half* src = srcB + (size_t)(mc * 128) * FC_;
#pragma unroll
        for (int t = 0; t < 3; t++)
#pragma unroll
            for (int i = 0; i < 2; i++) {
                int idx = i * 256 + tid;
                int r = idx >> 2, c = idx & 3;
                CP16(bs + t * 8192 + swz(r, c), src + (size_t)r * FC_ + t * 32 + c * 8);
            }
    };

    issueA(); issueB(0, 0); CPCOMMIT();   // group 0
    issueB(1, 1); CPCOMMIT();             // group 1

    __half* sp = g_s + (size_t)b * N_ * N_;
    const int gr = lane >> 2;
    const int qc = (lane & 3) * 2;

    for (int mc = 0; mc < 8; mc++) {
        if (mc < 7) { CPWAIT(1); } else { CPWAIT(0); }
        __syncthreads();

        const uint32_t BS = BS0 + (mc & 1) * SC_BUF;
        float acc[2][8][4];
#pragma unroll
        for (int mt = 0; mt < 2; mt++)
#pragma unroll
            for (int nt = 0; nt < 8; nt++)
#pragma unroll
                for (int j = 0; j < 4; j++) acc[mt][nt][j] = 0.f;

#pragma unroll
        for (int t = 0; t < 3; t++) {
#pragma unroll
            for (int ks = 0; ks < 2; ks++) {
                uint32_t af[2][4];
#pragma unroll
                for (int mt = 0; mt < 2; mt++) {
                    int row = wm * 32 + mt * 16 + ((lane >> 3) & 1) * 8 + (lane & 7);
                    int ch  = ks * 2 + (lane >> 4);
                    ldsm_x4(af[mt][0], af[mt][1], af[mt][2], af[mt][3],
                            AS + t * 8192 + swz(row, ch));
                }
                uint32_t bf[8][2];
#pragma unroll
                for (int p = 0; p < 4; p++) {
                    int row = wn * 64 + p * 16 + (lane >> 4) * 8 + (lane & 7);
                    int ch  = ks * 2 + ((lane >> 3) & 1);
                    uint32_t r0, r1, r2, r3;
                    ldsm_x4(r0, r1, r2, r3, BS + t * 8192 + swz(row, ch));
                    bf[2 * p][0] = r0; bf[2 * p][1] = r1;
                    bf[2 * p + 1][0] = r2; bf[2 * p + 1][1] = r3;
                }
#pragma unroll
                for (int mt = 0; mt < 2; mt++)
#pragma unroll
                    for (int nt = 0; nt < 8; nt++)
                        mma_fp16(acc[mt][nt], af[mt], bf[nt]);
            }
        }

        // Per-chunk epilogue: fp16 s tile [128 rows x 128 cols at mc*128]
#pragma unroll
        for (int mt = 0; mt < 2; mt++)
#pragma unroll
            for (int rr = 0; rr < 2; rr++) {
                int n = nBase + wm * 32 + mt * 16 + rr * 8 + gr;
#pragma unroll
                for (int nt = 0; nt < 8; nt++) {
                    int m = mc * 128 + wn * 64 + nt * 8 + qc;
                    __half2 v = __float22half2_rn(
                        make_float2(acc[mt][nt][rr * 2], acc[mt][nt][rr * 2 + 1]));
                    *reinterpret_cast<__half2*>(&sp[(size_t)n * N_ + m]) = v;
                }
            }
        __syncthreads();   // all warps done reading BS before reissue

        if (mc + 2 < 8) { issueB(mc & 1, mc + 2); CPCOMMIT(); }
    }
}

// ---------------------------------------------------------------------------
// Kernel 3: warp-per-row softmax over fp16 logits; writes fp16 beta.
// ---------------------------------------------------------------------------
__global__ __launch_bounds__(256) void k_softmax()
{
    const int wid  = threadIdx.x >> 5;
    const int lane = threadIdx.x & 31;
    const size_t row = (size_t)blockIdx.x * 8 + wid;
    const uint4* sp = reinterpret_cast<const uint4*>(g_s + row * N_);

    uint4 raw[4];
#pragma unroll
    for (int i = 0; i < 4; i++) raw[i] = sp[lane + 32 * i];

    float v[32];
#pragma unroll
    for (int i = 0; i < 4; i++) {
        const __half2* h2 = reinterpret_cast<const __half2*>(&raw[i]);
#pragma unroll
        for (int j = 0; j < 4; j++) {
            float2 f = __half22float2(h2[j]);
            v[i * 8 + j * 2]     = f.x;
            v[i * 8 + j * 2 + 1] = f.y;
        }
    }

    float m = -1e30f;
#pragma unroll
    for (int i = 0; i < 32; i++) m = fmaxf(m, v[i]);
#pragma unroll
    for (int o = 16; o > 0; o >>= 1)
        m = fmaxf(m, __shfl_xor_sync(0xFFFFFFFF, m, o));

    float sum = 0.f;
#pragma unroll
    for (int i = 0; i < 32; i++) { v[i] = __expf(v[i] - m); sum += v[i]; }
#pragma unroll
    for (int o = 16; o > 0; o >>= 1)
        sum += __shfl_xor_sync(0xFFFFFFFF, sum, o);
    const float inv = 1.0f / sum;

    uint4* bp = reinterpret_cast<uint4*>(g_beta + row * N_);
#pragma unroll
    for (int i = 0; i < 4; i++) {
        uint4 pk;
        __half2* h2 = reinterpret_cast<__half2*>(&pk);
#pragma unroll
        for (int j = 0; j < 4; j++)
            h2[j] = __float22half2_rn(make_float2(v[i * 8 + j * 2] * inv,
                                                  v[i * 8 + j * 2 + 1] * inv));
        bp[lane + 32 * i] = pk;
    }
}

// ---------------------------------------------------------------------------
// Kernel 4: fp16 HMMA GEMM  o[b] = beta[b] @ h_fl[b]  (M=1024, N=768, K=1024)
// CTA tile 128x128, BK=64 (2 subtiles/stage), 3-stage pipeline (96KB),
// 16 iterations (half the barriers). Epilogue fuses hw_recover + gamma*o + x.
// ---------------------------------------------------------------------------
constexpr int NKC_   = N_ / 64;    // 16 k-chunks of 64
constexpr int OSTAGE = 32768;      // A 16KB (2 subtiles) + B 16KB
constexpr int OSTGS  = 3;

__global__ __launch_bounds__(256) void k_o_mma(
    const float* __restrict__ x, const float* __restrict__ gammaP,
    float* __restrict__ out)
{
    extern __shared__ char smem[];
    const uint32_t sbase = smem_u32(smem);

    const int tid  = threadIdx.x;
    const int wid  = tid >> 5;
    const int lane = tid & 31;
    const int wm   = wid & 3;
    const int wn   = wid >> 2;
    const int b     = blockIdx.z;
    const int mBase = blockIdx.y * 128;
    const int cBase = blockIdx.x * 128;

    const __half* gA = g_beta + ((size_t)b * N_ + mBase) * N_;
    const __half* gB = g_hT  + ((size_t)b * HC_ + cBase) * N_;

    const int lr = tid >> 2;
    const int lc = tid & 3;

    auto issue = [&](int slot, int kc) {
        const uint32_t aS = sbase + slot * OSTAGE;
        const uint32_t bS = aS + 16384;
#pragma unroll
        for (int ksub = 0; ksub < 2; ksub++) {
            const int kOff = kc * 64 + ksub * 32 + lc * 8;
#pragma unroll
            for (int i = 0; i < 2; i++) {
                int r = lr + i * 64;
                CP16(aS + ksub * 8192 + swz(r, lc), gA + (size_t)r * N_ + kOff);
                CP16(bS + ksub * 8192 + swz(r, lc), gB + (size_t)r * N_ + kOff);
            }
        }
    };

    float acc[2][8][4];
#pragma unroll
    for (int mt = 0; mt < 2; mt++)
#pragma unroll
        for (int nt = 0; nt < 8; nt++)
#pragma unroll
            for (int j = 0; j < 4; j++) acc[mt][nt][j] = 0.f;

    issue(0, 0); CPCOMMIT();
    issue(1, 1); CPCOMMIT();

    for (int kc = 0; kc < NKC_; kc++) {
        if (kc + 2 < NKC_) {
            issue((kc + 2) % OSTGS, kc + 2); CPCOMMIT();
            CPWAIT(2);
        } else {
            CPWAIT(0);
        }
        __syncthreads();

        const uint32_t aS = sbase + (kc % OSTGS) * OSTAGE;
        const uint32_t bS = aS + 16384;
#pragma unroll
        for (int ksub = 0; ksub < 2; ksub++) {
            const uint32_t aT = aS + ksub * 8192;
            const uint32_t bT = bS + ksub * 8192;
#pragma unroll
            for (int ks = 0; ks < 2; ks++) {
                uint32_t afr[2][4];
#pragma unroll
                for (int mt = 0; mt < 2; mt++) {
                    int row = wm * 32 + mt * 16 + ((lane >> 3) & 1) * 8 + (lane & 7);
                    int ch  = ks * 2 + (lane >> 4);
                    ldsm_x4(afr[mt][0], afr[mt][1], afr[mt][2], afr[mt][3],
                            aT + swz(row, ch));
                }
                uint32_t bfr[8][2];
#pragma unroll
                for (int p = 0; p < 4; p++) {
                    int row = wn * 64 + p * 16 + (lane >> 4) * 8 + (lane & 7);
                    int ch  = ks * 2 + ((lane >> 3) & 1);
                    uint32_t r0, r1, r2, r3;
                    ldsm_x4(r0, r1, r2, r3, bT + swz(row, ch));
                    bfr[2 * p][0] = r0; bfr[2 * p][1] = r1;
                    bfr[2 * p + 1][0] = r2; bfr[2 * p + 1][1] = r3;
                }
#pragma unroll
                for (int mt = 0; mt < 2; mt++)
#pragma unroll
                    for (int nt = 0; nt < 8; nt++)
                        mma_fp16(acc[mt][nt], afr[mt], bfr[nt]);
            }
        }
        __syncthreads();
    }

    const float gamma = __ldg(gammaP);
    const int gr = lane >> 2;
    const int qc = (lane & 3) * 2;
#pragma unroll
    for (int mt = 0; mt < 2; mt++) {
#pragma unroll
        for (int rr = 0; rr < 2; rr++) {
            int m    = mBase + wm * 32 + mt * 16 + rr * 8 + gr;
            int hr   = m >> 8;
            int wpix = m & 255;
#pragma unroll
            for (int nt = 0; nt < 8; nt++) {
                int cg = cBase + wn * 64 + nt * 8 + qc;
                int sg = cg >> 8;
                int ch = cg & 255;
                int hh = sg * HS_ + hr;
                size_t idx = (((size_t)b * H_ + hh) * W_ + wpix) * C_ + ch;
                float2 xv = *reinterpret_cast<const float2*>(x + idx);
                float2 o;
                o.x = fmaf(gamma, acc[mt][nt][rr * 2 + 0], xv.x);
                o.y = fmaf(gamma, acc[mt][nt][rr * 2 + 1], xv.y);
                *reinterpret_cast<float2*>(out + idx) = o;
            }
        }
    }
}

// ---------------------------------------------------------------------------
extern "C" void kernel_launch(void* const* d_in, const int* in_sizes, int n_in,
                              void* d_out, int out_size)
{
    const float* x     = (const float*)d_in[0];
    const float* Wf    = (const float*)d_in[1];
    const float* Wg    = (const float*)d_in[2];
    const float* Wh    = (const float*)d_in[3];
    const float* gamma = (const float*)d_in[4];
    float* out = (float*)d_out;

    static bool attrSet = false;
    if (!attrSet) {
        cudaFuncSetAttribute(k_proj, cudaFuncAttributeMaxDynamicSharedMemorySize,
                             PJ_STGS * PJ_STAGE);
        cudaFuncSetAttribute(k_score_mma, cudaFuncAttributeMaxDynamicSharedMemorySize,
                             3 * SC_BUF);
        cudaFuncSetAttribute(k_o_mma, cudaFuncAttributeMaxDynamicSharedMemorySize,
                             OSTGS * OSTAGE);
        attrSet = true;
    }

    k_cvt_x    <<<P_ * C_ / 4 / 256, 256>>>(x);
    k_cvt_w    <<<320, 256>>>(Wf, Wg, Wh);
    k_proj     <<<dim3(5, P_ / 128), 256, PJ_STGS * PJ_STAGE>>>();
    k_score_mma<<<dim3(N_ / 128, B_), 256, 3 * SC_BUF>>>();
    k_softmax  <<<B_ * N_ / 8, 256>>>();
    k_o_mma    <<<dim3(HC_ / 128, N_ / 128, B_), 256,
                  OSTGS * OSTAGE>>>(x, gamma, out);
}